// round 17
// baseline (speedup 1.0000x reference)
#include <cuda_runtime.h>
#include <cuda_fp16.h>
#include <mma.h>
#include <math.h>

using namespace nvcuda;

#define NN      50000
#define NN_PAD  50016           // round up for tile-tail reads (zeros in pad)
#define NE      800000
#define F0      64
#define F0A     80              // K augmented: 64 feat + 1 bias + 15 zero pad
#define F1      128
#define F2      32
#define MAXDEG  96              // >> max degree of Poisson(16) over 50k nodes (~35)

// ---------------- scratch (static device globals) ----------------------------
__device__ __half2 g_xs[NN * 32];       // dinv[n]*x[n] fp16 payload (128B rows)
__device__ __half2 g_axh[NN_PAD * 32];  // aggregated x, fp16 row-major [n][64]
__device__ __half  g_h2h[NN * F2];      // dinv[n]*(a1@W2), fp16 (64B rows)
__device__ __half  g_W1h[F0 * F1];
__device__ __half  g_W2h[F1 * F2];
__device__ int     g_fill[NN];          // zero at load; counts after scatter; re-zeroed by agg2g3
__device__ int     g_colsrc[NN * MAXDEG];

// ---------------- Scatter into padded buckets (+ fp16 weight conversion) -----
__global__ void k_scatter(const int* __restrict__ src,
                          const int* __restrict__ dst,
                          const float* __restrict__ W1,
                          const float* __restrict__ W2) {
    int i = blockIdx.x * blockDim.x + threadIdx.x;
    if (i < F0 * F1) g_W1h[i] = __float2half(W1[i]);
    else if (i < F0 * F1 + F1 * F2) g_W2h[i - F0 * F1] = __float2half(W2[i - F0 * F1]);
    if (i < NE) {
        int d  = __ldg(&dst[i]);
        int sv = __ldg(&src[i]);
        int pos = atomicAdd(&g_fill[d], 1);
        g_colsrc[d * MAXDEG + pos] = sv;
    }
}

// ---------------- Prescale: xs = half2(dinv[n] * x[n]) ----------------------
__global__ void __launch_bounds__(256) k_prescale(const float* __restrict__ x) {
    int idx = blockIdx.x * 256 + threadIdx.x;     // over NN*32 half2 slots
    if (idx >= NN * 32) return;
    int n = idx >> 5;
    float dn = rsqrtf((float)(g_fill[n] + 1));    // +1 self loop
    float2 v = ((const float2*)x)[idx];
    g_xs[idx] = __floats2half2_rn(dn * v.x, dn * v.y);
}

// ---------------- Aggregate x: fp16 gathers -> fp16 ax ----------------------
__global__ void __launch_bounds__(256) k_aggx(const float* __restrict__ x) {
    int gtid = blockIdx.x * blockDim.x + threadIdx.x;
    int n = gtid >> 5;
    int lane = gtid & 31;
    if (n >= NN) return;

    int deg = g_fill[n];
    float dn = rsqrtf((float)(deg + 1));
    float2 sv = ((const float2*)x)[n * 32 + lane];
    float ax = dn * sv.x, ay = dn * sv.y;          // self term, fp32

    int e = n * MAXDEG, end = e + deg;
    for (; e + 7 < end; e += 8) {
        int si[8];
        #pragma unroll
        for (int u = 0; u < 8; u++) si[u] = g_colsrc[e + u];
        __half2 hv[8];
        #pragma unroll
        for (int u = 0; u < 8; u++) hv[u] = g_xs[si[u] * 32 + lane];
        #pragma unroll
        for (int u = 0; u < 8; u++) {
            float2 f = __half22float2(hv[u]);
            ax += f.x; ay += f.y;
        }
    }
    for (; e < end; e++) {
        float2 f = __half22float2(g_xs[g_colsrc[e] * 32 + lane]);
        ax += f.x; ay += f.y;
    }
    g_axh[n * 32 + lane] = __floats2half2_rn(dn * ax, dn * ay);
}

// ---- Fused WMMA GEMM1+GEMM2, M=64/block, bias-in-K, no fp32 C1 buffer ------
// smem bytes: sA 64x80x2=10240 | sW1 80x128x2=20480 | sW2 8192 | sB 64x128x2=16384 | sC2 64x32x4=8192
#define OFF_A   0
#define OFF_W1  10240
#define OFF_W2  30720
#define OFF_B   38912
#define OFF_C2  55296
#define G12_SMEM 63488
__global__ void __launch_bounds__(256) k_gemm12(const float* __restrict__ b1) {
    extern __shared__ unsigned char sm[];
    __half* sA  = (__half*)(sm + OFF_A);    // 64 x 80, row-major (bias col + pad)
    __half* sW1 = (__half*)(sm + OFF_W1);   // 80 x 128 (row 64 = b1, 65..79 = 0)
    __half* sW2 = (__half*)(sm + OFF_W2);   // 128 x 32
    __half* sB  = (__half*)(sm + OFF_B);    // 64 x 128, fp16 a1
    float*  sC2 = (float*)(sm + OFF_C2);    // 64 x 32

    int tid = threadIdx.x;
    int wid = tid >> 5;
    int n0 = blockIdx.x * 64;

    // ---- stage A (augmented): 64 rows x 40 half2 ----
    {
        __half2* A2 = (__half2*)sA;
        const __half2 one0 = __floats2half2_rn(1.f, 0.f);
        const __half2 zero = __floats2half2_rn(0.f, 0.f);
        for (int idx = tid; idx < 64 * 40; idx += 256) {
            int j = idx / 40, kk = idx % 40;
            __half2 v;
            if (kk < 32)      v = g_axh[(n0 + j) * 32 + kk];  // pad rows read zeros
            else if (kk == 32) v = one0;                       // bias column = 1
            else               v = zero;
            A2[j * 40 + kk] = v;
        }
    }
    // ---- stage W1 rows 0..63, then bias row 64 + zero rows 65..79 ----
    {
        const uint4* srcW1 = (const uint4*)g_W1h;
        uint4* dW1 = (uint4*)sW1;
        #pragma unroll
        for (int i = tid; i < 1024; i += 256) dW1[i] = srcW1[i];
        __half2* W12 = (__half2*)sW1;
        const __half2 zero = __floats2half2_rn(0.f, 0.f);
        for (int idx = tid; idx < 16 * 64; idx += 256) {    // rows 64..79
            int r = idx >> 6, c2 = idx & 63;
            __half2 v = zero;
            if (r == 0) v = __floats2half2_rn(__ldg(&b1[2 * c2]), __ldg(&b1[2 * c2 + 1]));
            W12[(64 + r) * 64 + c2] = v;
        }
        const uint4* srcW2 = (const uint4*)g_W2h;
        uint4* dW2 = (uint4*)sW2;
        #pragma unroll
        for (int i = tid; i < 512; i += 256) dW2[i] = srcW2[i];
    }
    __syncthreads();

    // ---- phase 1: sB = half(relu(A_aug @ W1_aug)), warp: 16 rows x 64 cols --
    {
        int r0 = (wid & 3) * 16;
        int c0 = (wid >> 2) * 64;
        wmma::fragment<wmma::accumulator, 16, 16, 16, float> acc[4];
        #pragma unroll
        for (int j = 0; j < 4; j++) wmma::fill_fragment(acc[j], 0.f);

        #pragma unroll
        for (int k = 0; k < F0A; k += 16) {
            wmma::fragment<wmma::matrix_a, 16, 16, 16, __half, wmma::row_major> af;
            wmma::load_matrix_sync(af, sA + r0 * F0A + k, F0A);
            #pragma unroll
            for (int j = 0; j < 4; j++) {
                wmma::fragment<wmma::matrix_b, 16, 16, 16, __half, wmma::row_major> bf;
                wmma::load_matrix_sync(bf, sW1 + k * F1 + c0 + 16 * j, F1);
                wmma::mma_sync(acc[j], af, bf, acc[j]);
            }
        }
        // relu in registers (position-independent), convert to fp16 fragment
        #pragma unroll
        for (int j = 0; j < 4; j++) {
            wmma::fragment<wmma::accumulator, 16, 16, 16, __half> hacc;
            #pragma unroll
            for (int e2 = 0; e2 < acc[j].num_elements; e2++)
                hacc.x[e2] = __float2half(fmaxf(acc[j].x[e2], 0.f));
            wmma::store_matrix_sync(sB + r0 * F1 + c0 + 16 * j, hacc, F1,
                                    wmma::mem_row_major);
        }
    }
    __syncthreads();

    // ---- phase 2: C2[64x32] = sB[64x128] @ W2[128x32]; warp: 16x16 tile ----
    {
        int r0 = (wid & 3) * 16;
        int c0 = (wid >> 2) * 16;
        wmma::fragment<wmma::accumulator, 16, 16, 16, float> acc;
        wmma::fill_fragment(acc, 0.f);
        #pragma unroll
        for (int k = 0; k < F1; k += 16) {
            wmma::fragment<wmma::matrix_a, 16, 16, 16, __half, wmma::row_major> af;
            wmma::fragment<wmma::matrix_b, 16, 16, 16, __half, wmma::row_major> bf;
            wmma::load_matrix_sync(af, sB + r0 * F1 + k, F1);
            wmma::load_matrix_sync(bf, sW2 + k * F2 + c0, F2);
            wmma::mma_sync(acc, af, bf, acc);
        }
        wmma::store_matrix_sync(sC2 + r0 * F2 + c0, acc, F2, wmma::mem_row_major);
    }
    __syncthreads();

    // ---- h2h[n] = half(dinv[n] * C2[n]) — 8 cols/thread, one uint4 store ---
    {
        int nl = tid >> 2;                   // 0..63
        int c  = (tid & 3) * 8;
        int n = n0 + nl;
        if (n < NN) {
            float dnn = rsqrtf((float)(g_fill[n] + 1));
            float4 v0 = *(float4*)&sC2[nl * F2 + c];
            float4 v1 = *(float4*)&sC2[nl * F2 + c + 4];
            union { __half2 h[4]; uint4 u; } pk;
            pk.h[0] = __floats2half2_rn(dnn * v0.x, dnn * v0.y);
            pk.h[1] = __floats2half2_rn(dnn * v0.z, dnn * v0.w);
            pk.h[2] = __floats2half2_rn(dnn * v1.x, dnn * v1.y);
            pk.h[3] = __floats2half2_rn(dnn * v1.z, dnn * v1.w);
            *(uint4*)&g_h2h[n * F2 + c] = pk.u;
        }
    }
}

// ------- Fused agg2 + classifier (fp16 gathers; re-zeroes fill) --------------
__global__ void __launch_bounds__(256) k_agg2g3(const float* __restrict__ b2,
                                                const float* __restrict__ Wc,
                                                const float* __restrict__ bc,
                                                float* __restrict__ out,
                                                float* __restrict__ hout) {
    __shared__ float sW[F2 * F2];
    int tid = threadIdx.x;
    for (int i = tid; i < F2 * F2; i += 256) sW[i] = Wc[i];
    __syncthreads();

    int gtid = blockIdx.x * 256 + tid;
    int n = gtid >> 5;
    int lane = gtid & 31;
    if (n >= NN) return;

    int deg = g_fill[n];
    float dn = rsqrtf((float)(deg + 1));
    float acc = __half2float(g_h2h[n * F2 + lane]);   // self term (pre-scaled)

    int e = n * MAXDEG, end = e + deg;
    for (; e + 7 < end; e += 8) {
        int si[8];
        #pragma unroll
        for (int u = 0; u < 8; u++) si[u] = g_colsrc[e + u];
        __half hv[8];
        #pragma unroll
        for (int u = 0; u < 8; u++) hv[u] = g_h2h[si[u] * F2 + lane];
        #pragma unroll
        for (int u = 0; u < 8; u++) acc += __half2float(hv[u]);
    }
    for (; e < end; e++)
        acc += __half2float(g_h2h[g_colsrc[e] * F2 + lane]);

    float h = dn * acc + b2[lane];
    hout[n * F2 + lane] = h;

    float o = 0.f;
    #pragma unroll
    for (int k = 0; k < F2; k++) {
        float hk = __shfl_sync(0xFFFFFFFFu, h, k);
        o = fmaf(hk, sW[k * F2 + lane], o);
    }
    out[n * F2 + lane] = o + bc[lane];

    if (lane == 0) g_fill[n] = 0;                    // reset for next replay
}

// ---------------- launch -----------------------------------------------------
extern "C" void kernel_launch(void* const* d_in, const int* in_sizes, int n_in,
                              void* d_out, int out_size) {
    const float* x   = (const float*)d_in[0];
    const int*   ei  = (const int*)d_in[1];
    const float* W1  = (const float*)d_in[2];
    const float* b1  = (const float*)d_in[3];
    const float* W2  = (const float*)d_in[4];
    const float* b2  = (const float*)d_in[5];
    const float* Wc  = (const float*)d_in[6];
    const float* bc  = (const float*)d_in[7];

    const int* src = ei;
    const int* dst = ei + NE;

    float* out  = (float*)d_out;            // [NN, F2]
    float* hout = (float*)d_out + NN * F2;  // [NN, F2]

    static int smem_set = 0;
    if (!smem_set) {
        cudaFuncSetAttribute(k_gemm12, cudaFuncAttributeMaxDynamicSharedMemorySize,
                             G12_SMEM);
        smem_set = 1;
    }

    int nb_edges = (NE + 255) / 256;
    int nb_gemm  = (NN + 63) / 64;

    // Padded-bucket CSR in ONE atomic pass (fill starts zero; counts emerge)
    k_scatter<<<nb_edges, 256>>>(src, dst, W1, W2);

    // Layer 1: prescale (fp16 payload) -> aggregate -> fused WMMA gemm1+gemm2
    k_prescale<<<(NN * 32 + 255) / 256, 256>>>(x);
    k_aggx<<<(NN * 32 + 255) / 256, 256>>>(x);
    k_gemm12<<<nb_gemm, 256, G12_SMEM>>>(b1);

    // agg2 + classifier fused (fp16 gathers; zeroes fill for next replay)
    k_agg2g3<<<(NN * 32 + 255) / 256, 256>>>(b2, Wc, bc, out, hout);
}